// round 4
// baseline (speedup 1.0000x reference)
#include <cuda_runtime.h>
#include <cuda_fp16.h>
#include <cstdint>

// ---------------------------------------------------------------------------
// CFConvAngular: warp-MMA + ldmatrix, 512-thread CTA (16 warps).
// B=2, A=512, T=512, F=128, n_rbf=25. One CTA per (b,a). T tiled by 128.
// Per tile:  H1 = ssp(r@Wf1+bf1)            (FFMA2 fp32 -> fp16 SMEM)
//            D^T[f][t] = Wf2^T @ H1^T       (mma.sync, A frags in regs,
//                                            B frags via ldmatrix.x4)
//            acc[f] += (D+bf2[f]) * y[j(t)][f]*y[k(t)][f]*m[t]
// Final:     out = ssp(acc @ Wout + bout)
// Warp w: f-block (w&7)*16, t-half (w>>3)*64.
// ---------------------------------------------------------------------------

#define B_DIM 2
#define A_DIM 512
#define T_DIM 512
#define F_DIM 128
#define R_DIM 25
#define TT    128
#define NTILES (T_DIM / TT)     // 4
#define NT    512               // 16 warps

__device__ float g_y[B_DIM * A_DIM * F_DIM];

// ---------------- f32x2 helpers (GEMM1) ----------------
typedef unsigned long long u64t;
__device__ __forceinline__ u64t pk2(float lo, float hi) {
    u64t r; asm("mov.b64 %0, {%1,%2};" : "=l"(r) : "f"(lo), "f"(hi)); return r;
}
__device__ __forceinline__ u64t dup2(float x) { return pk2(x, x); }
__device__ __forceinline__ void up2(u64t v, float& lo, float& hi) {
    asm("mov.b64 {%0,%1}, %2;" : "=f"(lo), "=f"(hi) : "l"(v));
}
__device__ __forceinline__ u64t fma2_(u64t a, u64t b, u64t c) {
    u64t d; asm("fma.rn.f32x2 %0, %1, %2, %3;" : "=l"(d) : "l"(a), "l"(b), "l"(c)); return d;
}

__device__ __forceinline__ uint32_t smem_u32(const void* p) {
    uint32_t a;
    asm("{ .reg .u64 t; cvta.to.shared.u64 t, %1; cvt.u32.u64 %0, t; }" : "=r"(a) : "l"(p));
    return a;
}

// shifted softplus
__device__ __forceinline__ float sspf(float v) {
    float e = __expf(-fabsf(v));
    return fmaxf(v, 0.0f) + __logf(1.0f + e) - 0.69314718055994530942f;
}

// mma.sync m16n8k16 row.col f32 = f16 * f16 + f32
__device__ __forceinline__ void mma16816(float& c0, float& c1, float& c2, float& c3,
                                         uint32_t a0, uint32_t a1, uint32_t a2, uint32_t a3,
                                         uint32_t b0, uint32_t b1) {
    asm volatile("mma.sync.aligned.m16n8k16.row.col.f32.f16.f16.f32 "
                 "{%0,%1,%2,%3}, {%4,%5,%6,%7}, {%8,%9}, {%0,%1,%2,%3};"
                 : "+f"(c0), "+f"(c1), "+f"(c2), "+f"(c3)
                 : "r"(a0), "r"(a1), "r"(a2), "r"(a3), "r"(b0), "r"(b1));
}

// ldmatrix x4: 4 consecutive 8x8 f16 matrices (rows=t, cols=k)
__device__ __forceinline__ void ldsm_x4(uint32_t& r0, uint32_t& r1,
                                        uint32_t& r2, uint32_t& r3, uint32_t addr) {
    asm volatile("ldmatrix.sync.aligned.m8n8.x4.shared.b16 {%0,%1,%2,%3}, [%4];"
                 : "=r"(r0), "=r"(r1), "=r"(r2), "=r"(r3) : "r"(addr));
}

// ------------------------- kernel 1: y = x @ Win ---------------------------
__global__ void __launch_bounds__(F_DIM) in2f_kernel(
    const float* __restrict__ x, const float* __restrict__ Win)
{
    __shared__ float sx[F_DIM];
    const int tid = threadIdx.x;
    const int blk = blockIdx.x;
    sx[tid] = x[blk * F_DIM + tid];
    __syncthreads();
    float s0 = 0.f, s1 = 0.f, s2 = 0.f, s3 = 0.f;
#pragma unroll
    for (int i = 0; i < F_DIM; i += 4) {
        s0 = fmaf(sx[i + 0], Win[(i + 0) * F_DIM + tid], s0);
        s1 = fmaf(sx[i + 1], Win[(i + 1) * F_DIM + tid], s1);
        s2 = fmaf(sx[i + 2], Win[(i + 2) * F_DIM + tid], s2);
        s3 = fmaf(sx[i + 3], Win[(i + 3) * F_DIM + tid], s3);
    }
    g_y[blk * F_DIM + tid] = (s0 + s1) + (s2 + s3);
}

// ------------------------- main fused kernel -------------------------------
#define H1_STRIDE_B 272
#define OFF_H1   0                        // 128*272 = 34816
#define OFF_WF1  34816                    // 25*128 f32 = 12800
#define OFF_R    47616                    // 128*26 f32 = 13312
#define OFF_J    60928                    // 128 int
#define OFF_K    61440                    // 128 int
#define OFF_M    61952                    // 128 f32
#define OFF_ACC  62464                    // 128 f32
#define OFF_RED  62976                    // 2*128 f32 = 1024
#define SMEM_BYTES 64000

__global__ void __launch_bounds__(NT, 1) cfconv_kernel(
    const float* __restrict__ r_ij, const float* __restrict__ mask,
    const float* __restrict__ Wf1, const float* __restrict__ bf1,
    const float* __restrict__ Wf2, const float* __restrict__ bf2,
    const float* __restrict__ Wout, const float* __restrict__ bout,
    const int* __restrict__ nj, const int* __restrict__ nk,
    float* __restrict__ out)
{
    extern __shared__ char smem[];
    const int tid  = threadIdx.x;
    const int wid  = tid >> 5;            // 0..15
    const int lane = tid & 31;
    const int g    = lane >> 2;           // 0..7
    const int tig  = lane & 3;            // 0..3
    const int blk  = blockIdx.x;
    const int b    = blk >> 9;

    const int fblk  = wid & 7;            // f-block (16 f each)
    const int thalf = wid >> 3;           // 0/1: t-half (64 t each)

    float* sWf1 = (float*)(smem + OFF_WF1);
    float* sR   = (float*)(smem + OFF_R);
    int*   sJ   = (int*)(smem + OFF_J);
    int*   sK   = (int*)(smem + OFF_K);
    float* sM   = (float*)(smem + OFF_M);
    float* sAcc = (float*)(smem + OFF_ACC);
    float* sRed = (float*)(smem + OFF_RED);
    const uint32_t sH1u = smem_u32(smem + OFF_H1);

    // ---- stage Wf1 (fp32) ----
    for (int e = tid; e < R_DIM * F_DIM; e += NT) sWf1[e] = Wf1[e];

    // ---- loop-invariant A frags: A = Wf2^T[f][k] row-major, warp f-rows ----
    const int fw   = fblk * 16;
    const int f_lo = fw + g;
    const int f_hi = fw + g + 8;
    uint32_t aA[8][4];
#pragma unroll
    for (int ks = 0; ks < 8; ks++) {
        const int k0 = ks * 16 + tig * 2;
        __half2 h;
        h = __floats2half2_rn(Wf2[k0 * F_DIM + f_lo], Wf2[(k0 + 1) * F_DIM + f_lo]);
        aA[ks][0] = *(uint32_t*)&h;
        h = __floats2half2_rn(Wf2[k0 * F_DIM + f_hi], Wf2[(k0 + 1) * F_DIM + f_hi]);
        aA[ks][1] = *(uint32_t*)&h;
        h = __floats2half2_rn(Wf2[(k0 + 8) * F_DIM + f_lo], Wf2[(k0 + 9) * F_DIM + f_lo]);
        aA[ks][2] = *(uint32_t*)&h;
        h = __floats2half2_rn(Wf2[(k0 + 8) * F_DIM + f_hi], Wf2[(k0 + 9) * F_DIM + f_hi]);
        aA[ks][3] = *(uint32_t*)&h;
    }
    const float bf2_lo = bf2[f_lo];
    const float bf2_hi = bf2[f_hi];

    // ---- GEMM1 mapping: kg = k-block of 16, tq -> 2 t-rows ----
    const int kg = tid & 7;
    const int tq = tid >> 3;              // 0..63
    u64t bf1p[8];
#pragma unroll
    for (int p = 0; p < 8; p++)
        bf1p[p] = pk2(bf1[kg * 16 + 2 * p], bf1[kg * 16 + 2 * p + 1]);

    // per-lane ldmatrix row offset (matrix m = lane>>3, row r = lane&7)
    const uint32_t lds_rowoff = (uint32_t)((lane & 7) * H1_STRIDE_B + (lane >> 3) * 16);

    const long   rbase = (long)blk * T_DIM * R_DIM;
    const int    tbase = blk * T_DIM;
    const float* ybase = g_y + (long)b * A_DIM * F_DIM;

    float acc_lo = 0.f, acc_hi = 0.f;

    for (int tile = 0; tile < NTILES; ++tile) {
        // ---- stage r tile + indices ----
        {
            const long roff = rbase + (long)tile * TT * R_DIM;
            for (int e = tid; e < TT * R_DIM; e += NT)
                sR[(e / R_DIM) * 26 + (e % R_DIM)] = r_ij[roff + e];
            const int toff = tbase + tile * TT;
            if (tid < TT) {
                sJ[tid] = nj[toff + tid];
                sK[tid] = nk[toff + tid];
                sM[tid] = mask[toff + tid];
            }
        }
        __syncthreads();

        // ---- GEMM1: H1[t][k] = ssp(r@Wf1+bf1), 2 t-rows x 16 k per thread ----
        {
            u64t h[2][8];
#pragma unroll
            for (int i = 0; i < 2; i++)
#pragma unroll
                for (int p = 0; p < 8; p++) h[i][p] = bf1p[p];

#pragma unroll 5
            for (int r = 0; r < R_DIM; r++) {
                const float* wrow = &sWf1[r * F_DIM + kg * 16];
                const float4 w0 = *(const float4*)(wrow + 0);
                const float4 w1 = *(const float4*)(wrow + 4);
                const float4 w2 = *(const float4*)(wrow + 8);
                const float4 w3 = *(const float4*)(wrow + 12);
                const u64t wb[8] = { pk2(w0.x, w0.y), pk2(w0.z, w0.w),
                                     pk2(w1.x, w1.y), pk2(w1.z, w1.w),
                                     pk2(w2.x, w2.y), pk2(w2.z, w2.w),
                                     pk2(w3.x, w3.y), pk2(w3.z, w3.w) };
#pragma unroll
                for (int i = 0; i < 2; i++) {
                    const u64t a = dup2(sR[(tq * 2 + i) * 26 + r]);
#pragma unroll
                    for (int p = 0; p < 8; p++) h[i][p] = fma2_(a, wb[p], h[i][p]);
                }
            }
            // ssp -> fp16 -> SMEM
#pragma unroll
            for (int i = 0; i < 2; i++) {
                const int t = tq * 2 + i;
                uint32_t u[8];
#pragma unroll
                for (int p = 0; p < 8; p++) {
                    float lo, hi; up2(h[i][p], lo, hi);
                    __half2 hh = __floats2half2_rn(sspf(lo), sspf(hi));
                    u[p] = *(uint32_t*)&hh;
                }
                char* dst = smem + OFF_H1 + t * H1_STRIDE_B + kg * 32;
                *(uint4*)(dst)      = make_uint4(u[0], u[1], u[2], u[3]);
                *(uint4*)(dst + 16) = make_uint4(u[4], u[5], u[6], u[7]);
            }
        }
        __syncthreads();

        // ---- MMA + epilogue over this warp's 8 t-blocks ----
#pragma unroll 2
        for (int nb = 0; nb < 8; nb++) {
            const int nbg = thalf * 8 + nb;           // global 8-t block
            const uint32_t bbase = sH1u + (uint32_t)(nbg * 8 * H1_STRIDE_B) + lds_rowoff;

            float c0 = 0.f, c1 = 0.f, c2 = 0.f, c3 = 0.f;
#pragma unroll
            for (int kq = 0; kq < 4; kq++) {
                uint32_t q0, q1, q2, q3;
                ldsm_x4(q0, q1, q2, q3, bbase + kq * 64);
                mma16816(c0, c1, c2, c3,
                         aA[2 * kq][0], aA[2 * kq][1], aA[2 * kq][2], aA[2 * kq][3],
                         q0, q1);
                mma16816(c0, c1, c2, c3,
                         aA[2 * kq + 1][0], aA[2 * kq + 1][1], aA[2 * kq + 1][2], aA[2 * kq + 1][3],
                         q2, q3);
            }
            // epilogue: thread holds D^T[f_lo/f_hi][t_a/t_b]
            const int t_a = nbg * 8 + tig * 2;
            const int t_b = t_a + 1;
            const int ja = sJ[t_a], ka = sK[t_a];
            const int jb = sJ[t_b], kb = sK[t_b];
            const float ma = sM[t_a], mb = sM[t_b];
            const float* yja = ybase + ja * F_DIM;
            const float* yka = ybase + ka * F_DIM;
            const float* yjb = ybase + jb * F_DIM;
            const float* ykb = ybase + kb * F_DIM;
            const float za_lo = yja[f_lo] * yka[f_lo] * ma;
            const float za_hi = yja[f_hi] * yka[f_hi] * ma;
            const float zb_lo = yjb[f_lo] * ykb[f_lo] * mb;
            const float zb_hi = yjb[f_hi] * ykb[f_hi] * mb;
            acc_lo = fmaf(c0 + bf2_lo, za_lo, acc_lo);
            acc_lo = fmaf(c1 + bf2_lo, zb_lo, acc_lo);
            acc_hi = fmaf(c2 + bf2_hi, za_hi, acc_hi);
            acc_hi = fmaf(c3 + bf2_hi, zb_hi, acc_hi);
        }
        __syncthreads();   // protect H1/sR/sJ for next tile
    }

    // ---- reduce over quad (tig) and publish per-t-half partials ----
    acc_lo += __shfl_xor_sync(0xFFFFFFFF, acc_lo, 1);
    acc_lo += __shfl_xor_sync(0xFFFFFFFF, acc_lo, 2);
    acc_hi += __shfl_xor_sync(0xFFFFFFFF, acc_hi, 1);
    acc_hi += __shfl_xor_sync(0xFFFFFFFF, acc_hi, 2);
    if (tig == 0) {
        sRed[thalf * F_DIM + f_lo] = acc_lo;
        sRed[thalf * F_DIM + f_hi] = acc_hi;
    }
    __syncthreads();
    if (tid < F_DIM) sAcc[tid] = sRed[tid] + sRed[F_DIM + tid];
    __syncthreads();

    // ---- f2out ----
    if (tid < F_DIM) {
        float s0 = 0.f, s1 = 0.f, s2 = 0.f, s3 = 0.f;
#pragma unroll
        for (int f = 0; f < F_DIM; f += 4) {
            s0 = fmaf(sAcc[f + 0], Wout[(f + 0) * F_DIM + tid], s0);
            s1 = fmaf(sAcc[f + 1], Wout[(f + 1) * F_DIM + tid], s1);
            s2 = fmaf(sAcc[f + 2], Wout[(f + 2) * F_DIM + tid], s2);
            s3 = fmaf(sAcc[f + 3], Wout[(f + 3) * F_DIM + tid], s3);
        }
        out[blk * F_DIM + tid] = sspf((s0 + s1) + (s2 + s3) + bout[tid]);
    }
}

// ------------------------------- launcher ----------------------------------
extern "C" void kernel_launch(void* const* d_in, const int* in_sizes, int n_in,
                              void* d_out, int out_size)
{
    const float* x    = (const float*)d_in[0];
    const float* r_ij = (const float*)d_in[1];
    const float* mask = (const float*)d_in[2];
    const float* Wf1  = (const float*)d_in[3];
    const float* bf1  = (const float*)d_in[4];
    const float* Wf2  = (const float*)d_in[5];
    const float* bf2  = (const float*)d_in[6];
    const float* Win  = (const float*)d_in[7];
    const float* Wout = (const float*)d_in[8];
    const float* bout = (const float*)d_in[9];
    const int*   nj   = (const int*)d_in[10];
    const int*   nk   = (const int*)d_in[11];
    float* out = (float*)d_out;

    cudaFuncSetAttribute(cfconv_kernel,
                         cudaFuncAttributeMaxDynamicSharedMemorySize, SMEM_BYTES);

    in2f_kernel<<<B_DIM * A_DIM, F_DIM>>>(x, Win);
    cfconv_kernel<<<B_DIM * A_DIM, NT, SMEM_BYTES>>>(
        r_ij, mask, Wf1, bf1, Wf2, bf2, Wout, bout, nj, nk, out);
}

// round 5
// speedup vs baseline: 3.0314x; 3.0314x over previous
#include <cuda_runtime.h>
#include <cuda_fp16.h>
#include <cstdint>

// ---------------------------------------------------------------------------
// CFConvAngular: all-MMA version. 256 threads (8 warps), 2 CTAs/SM.
// GEMM1: H1^T[k][t] = Wf1^T @ R^T   (mma.sync, A=Wf1^T frags in regs,
//                                    B via ldmatrix from fp16 r-tile, K=32 pad)
//        + bf1 + ssp applied on C frags -> fp16 H1^T in SMEM (272B rows)
// GEMM2: D^T[f][t] = Wf2^T @ H1^T   (mma.sync, A=Wf2^T frags in regs,
//                                    B via ldmatrix.x4.trans on H1^T)
// epilogue: acc[f] += (D+bf2[f]) * y[j(t)][f]*y[k(t)][f]*m[t]
// out = ssp(acc @ Wout + bout)
// ---------------------------------------------------------------------------

#define B_DIM 2
#define A_DIM 512
#define T_DIM 512
#define F_DIM 128
#define R_DIM 25
#define TT    128
#define NTILES (T_DIM / TT)     // 4
#define NT    256               // 8 warps

__device__ float g_y[B_DIM * A_DIM * F_DIM];

__device__ __forceinline__ uint32_t smem_u32(const void* p) {
    uint32_t a;
    asm("{ .reg .u64 t; cvta.to.shared.u64 t, %1; cvt.u32.u64 %0, t; }" : "=r"(a) : "l"(p));
    return a;
}

// shifted softplus
__device__ __forceinline__ float sspf(float v) {
    float e = __expf(-fabsf(v));
    return fmaxf(v, 0.0f) + __logf(1.0f + e) - 0.69314718055994530942f;
}

// mma.sync m16n8k16 row.col f32 = f16*f16 + f32
__device__ __forceinline__ void mma16816(float& c0, float& c1, float& c2, float& c3,
                                         uint32_t a0, uint32_t a1, uint32_t a2, uint32_t a3,
                                         uint32_t b0, uint32_t b1) {
    asm volatile("mma.sync.aligned.m16n8k16.row.col.f32.f16.f16.f32 "
                 "{%0,%1,%2,%3}, {%4,%5,%6,%7}, {%8,%9}, {%0,%1,%2,%3};"
                 : "+f"(c0), "+f"(c1), "+f"(c2), "+f"(c3)
                 : "r"(a0), "r"(a1), "r"(a2), "r"(a3), "r"(b0), "r"(b1));
}

__device__ __forceinline__ void ldsm_x4(uint32_t& r0, uint32_t& r1,
                                        uint32_t& r2, uint32_t& r3, uint32_t addr) {
    asm volatile("ldmatrix.sync.aligned.m8n8.x4.shared.b16 {%0,%1,%2,%3}, [%4];"
                 : "=r"(r0), "=r"(r1), "=r"(r2), "=r"(r3) : "r"(addr));
}
__device__ __forceinline__ void ldsm_x4_t(uint32_t& r0, uint32_t& r1,
                                          uint32_t& r2, uint32_t& r3, uint32_t addr) {
    asm volatile("ldmatrix.sync.aligned.m8n8.x4.trans.shared.b16 {%0,%1,%2,%3}, [%4];"
                 : "=r"(r0), "=r"(r1), "=r"(r2), "=r"(r3) : "r"(addr));
}

__device__ __forceinline__ uint32_t h2u(float a, float b) {
    __half2 h = __floats2half2_rn(a, b);
    return *(uint32_t*)&h;
}

// ------------------------- kernel 1: y = x @ Win ---------------------------
__global__ void __launch_bounds__(F_DIM) in2f_kernel(
    const float* __restrict__ x, const float* __restrict__ Win)
{
    __shared__ float sx[F_DIM];
    const int tid = threadIdx.x;
    const int blk = blockIdx.x;
    sx[tid] = x[blk * F_DIM + tid];
    __syncthreads();
    float s0 = 0.f, s1 = 0.f, s2 = 0.f, s3 = 0.f;
#pragma unroll
    for (int i = 0; i < F_DIM; i += 4) {
        s0 = fmaf(sx[i + 0], Win[(i + 0) * F_DIM + tid], s0);
        s1 = fmaf(sx[i + 1], Win[(i + 1) * F_DIM + tid], s1);
        s2 = fmaf(sx[i + 2], Win[(i + 2) * F_DIM + tid], s2);
        s3 = fmaf(sx[i + 3], Win[(i + 3) * F_DIM + tid], s3);
    }
    g_y[blk * F_DIM + tid] = (s0 + s1) + (s2 + s3);
}

// ------------------------- main fused kernel -------------------------------
#define H1T_STRIDE_B 272                 // 128 k-rows x (128 t + pad) fp16
#define RH_STRIDE_B  80                  // 128 t-rows x (32 r + pad) fp16
#define OFF_H1T  0                       // 128*272 = 34816
#define OFF_RH   34816                   // 128*80  = 10240 -> 45056
#define OFF_J    45056                   // 128 int
#define OFF_K    45568                   // 128 int
#define OFF_M    46080                   // 128 f32
#define OFF_ACC  46592                   // 128 f32
#define SMEM_BYTES 47104

__global__ void __launch_bounds__(NT, 2) cfconv_kernel(
    const float* __restrict__ r_ij, const float* __restrict__ mask,
    const float* __restrict__ Wf1, const float* __restrict__ bf1,
    const float* __restrict__ Wf2, const float* __restrict__ bf2,
    const float* __restrict__ Wout, const float* __restrict__ bout,
    const int* __restrict__ nj, const int* __restrict__ nk,
    float* __restrict__ out)
{
    extern __shared__ char smem[];
    const int tid  = threadIdx.x;
    const int wid  = tid >> 5;            // 0..7
    const int lane = tid & 31;
    const int g    = lane >> 2;           // 0..7
    const int tig  = lane & 3;            // 0..3
    const int blk  = blockIdx.x;
    const int b    = blk >> 9;

    int*   sJ   = (int*)(smem + OFF_J);
    int*   sK   = (int*)(smem + OFF_K);
    float* sM   = (float*)(smem + OFF_M);
    float* sAcc = (float*)(smem + OFF_ACC);
    const uint32_t sH1Tu = smem_u32(smem + OFF_H1T);
    const uint32_t sRHu  = smem_u32(smem + OFF_RH);
    __half* sRh = (__half*)(smem + OFF_RH);

    // ---- warp row-block (used as kc-rows in GEMM1, f-rows in GEMM2) ----
    const int rw   = wid * 16;
    const int m_lo = rw + g;              // kc_lo / f_lo
    const int m_hi = rw + g + 8;          // kc_hi / f_hi

    // ---- GEMM1 A-frags: Wf1^T[kc][r], K=32 (r>=25 zero), loop-invariant ----
    uint32_t aW[2][4];
#pragma unroll
    for (int s = 0; s < 2; s++) {
        const int r0 = s * 16 + 2 * tig;
#pragma unroll
        for (int q = 0; q < 4; q++) {
            const int rr = r0 + (q >> 1) * 8;       // q=0,1 -> r0 ; q=2,3 -> r0+8
            const int cc = (q & 1) ? m_hi : m_lo;
            const float v0 = (rr     < R_DIM) ? Wf1[rr * F_DIM + cc]       : 0.f;
            const float v1 = (rr + 1 < R_DIM) ? Wf1[(rr + 1) * F_DIM + cc] : 0.f;
            aW[s][q] = h2u(v0, v1);
        }
    }
    // NOTE: frag order must be (row g k-pair, row g+8 k-pair, row g k+8, row g+8 k+8)
    // aW[s] = {a0,a1,a2,a3} with a0=(m_lo,r0), a1=(m_hi,r0), a2=(m_lo,r0+8), a3=(m_hi,r0+8)
    // (matches q mapping above: q0->(m_lo,rr=r0), q1->(m_hi,r0), q2->(m_lo,r0+8), q3->(m_hi,r0+8))

    // ---- GEMM2 A-frags: Wf2^T[f][k], loop-invariant (same recipe as R3) ----
    uint32_t aA[8][4];
#pragma unroll
    for (int ks = 0; ks < 8; ks++) {
        const int k0 = ks * 16 + tig * 2;
        aA[ks][0] = h2u(Wf2[k0 * F_DIM + m_lo],       Wf2[(k0 + 1) * F_DIM + m_lo]);
        aA[ks][1] = h2u(Wf2[k0 * F_DIM + m_hi],       Wf2[(k0 + 1) * F_DIM + m_hi]);
        aA[ks][2] = h2u(Wf2[(k0 + 8) * F_DIM + m_lo], Wf2[(k0 + 9) * F_DIM + m_lo]);
        aA[ks][3] = h2u(Wf2[(k0 + 8) * F_DIM + m_hi], Wf2[(k0 + 9) * F_DIM + m_hi]);
    }
    const float bf1_lo = bf1[m_lo], bf1_hi = bf1[m_hi];
    const float bf2_lo = bf2[m_lo], bf2_hi = bf2[m_hi];

    // ldmatrix lane addresses
    const uint32_t rh_off  = (uint32_t)((lane & 7) * RH_STRIDE_B + (lane >> 3) * 16);
    const uint32_t h1t_off = (uint32_t)(((lane >> 3) * 8 + (lane & 7)) * H1T_STRIDE_B);

    const long   rbase = (long)blk * T_DIM * R_DIM;
    const int    tbase = blk * T_DIM;
    const float* ybase = g_y + (long)b * A_DIM * F_DIM;

    float acc_lo = 0.f, acc_hi = 0.f;

    for (int tile = 0; tile < NTILES; ++tile) {
        // ---- stage r tile as fp16 [t][32] (r>=25 zeroed) + indices ----
        {
            const float* rsrc = r_ij + rbase + (long)tile * TT * R_DIM;
            for (int e = tid; e < TT * 32; e += NT) {
                const int t = e >> 5, r = e & 31;
                const float v = (r < R_DIM) ? rsrc[t * R_DIM + r] : 0.f;
                sRh[t * (RH_STRIDE_B / 2) + r] = __float2half_rn(v);
            }
            const int toff = tbase + tile * TT;
            if (tid < TT) {
                sJ[tid] = nj[toff + tid];
                sK[tid] = nk[toff + tid];
                sM[tid] = mask[toff + tid];
            }
        }
        __syncthreads();

        // ---- GEMM1: H1^T[kc][t] = Wf1^T @ R^T, then +bf1, ssp, fp16 store ----
#pragma unroll 4
        for (int nb = 0; nb < 16; nb++) {
            uint32_t q0, q1, q2, q3;
            ldsm_x4(q0, q1, q2, q3, sRHu + (uint32_t)(nb * 8 * RH_STRIDE_B) + rh_off);
            float c0 = 0.f, c1 = 0.f, c2 = 0.f, c3 = 0.f;
            mma16816(c0, c1, c2, c3, aW[0][0], aW[0][1], aW[0][2], aW[0][3], q0, q1);
            mma16816(c0, c1, c2, c3, aW[1][0], aW[1][1], aW[1][2], aW[1][3], q2, q3);
            const int t0 = nb * 8 + 2 * tig;
            const uint32_t u_lo = h2u(sspf(c0 + bf1_lo), sspf(c1 + bf1_lo));
            const uint32_t u_hi = h2u(sspf(c2 + bf1_hi), sspf(c3 + bf1_hi));
            *(uint32_t*)(smem + OFF_H1T + m_lo * H1T_STRIDE_B + t0 * 2) = u_lo;
            *(uint32_t*)(smem + OFF_H1T + m_hi * H1T_STRIDE_B + t0 * 2) = u_hi;
        }
        __syncthreads();

        // ---- GEMM2 + epilogue over 16 t-blocks ----
#pragma unroll 2
        for (int nb = 0; nb < 16; nb++) {
            float c0 = 0.f, c1 = 0.f, c2 = 0.f, c3 = 0.f;
#pragma unroll
            for (int kq = 0; kq < 4; kq++) {
                uint32_t q0, q1, q2, q3;
                // trans-ldsm: rows = kc (kq*32 + lane-pattern), col-block = nb
                ldsm_x4_t(q0, q1, q2, q3,
                          sH1Tu + (uint32_t)(kq * 32 * H1T_STRIDE_B) + h1t_off
                                + (uint32_t)(nb * 16));
                mma16816(c0, c1, c2, c3,
                         aA[2 * kq][0], aA[2 * kq][1], aA[2 * kq][2], aA[2 * kq][3],
                         q0, q1);
                mma16816(c0, c1, c2, c3,
                         aA[2 * kq + 1][0], aA[2 * kq + 1][1], aA[2 * kq + 1][2], aA[2 * kq + 1][3],
                         q2, q3);
            }
            // epilogue: thread holds D^T[m_lo/m_hi][t_a/t_b]
            const int t_a = nb * 8 + tig * 2;
            const int t_b = t_a + 1;
            const int ja = sJ[t_a], ka = sK[t_a];
            const int jb = sJ[t_b], kb = sK[t_b];
            const float ma = sM[t_a], mb = sM[t_b];
            const float* yja = ybase + ja * F_DIM;
            const float* yka = ybase + ka * F_DIM;
            const float* yjb = ybase + jb * F_DIM;
            const float* ykb = ybase + kb * F_DIM;
            const float za_lo = yja[m_lo] * yka[m_lo] * ma;
            const float za_hi = yja[m_hi] * yka[m_hi] * ma;
            const float zb_lo = yjb[m_lo] * ykb[m_lo] * mb;
            const float zb_hi = yjb[m_hi] * ykb[m_hi] * mb;
            acc_lo = fmaf(c0 + bf2_lo, za_lo, acc_lo);
            acc_lo = fmaf(c1 + bf2_lo, zb_lo, acc_lo);
            acc_hi = fmaf(c2 + bf2_hi, za_hi, acc_hi);
            acc_hi = fmaf(c3 + bf2_hi, zb_hi, acc_hi);
        }
        __syncthreads();
    }

    // ---- quad reduction and publish ----
    acc_lo += __shfl_xor_sync(0xFFFFFFFF, acc_lo, 1);
    acc_lo += __shfl_xor_sync(0xFFFFFFFF, acc_lo, 2);
    acc_hi += __shfl_xor_sync(0xFFFFFFFF, acc_hi, 1);
    acc_hi += __shfl_xor_sync(0xFFFFFFFF, acc_hi, 2);
    if (tig == 0) {
        sAcc[m_lo] = acc_lo;
        sAcc[m_hi] = acc_hi;
    }
    __syncthreads();

    // ---- f2out ----
    if (tid < F_DIM) {
        float s0 = 0.f, s1 = 0.f, s2 = 0.f, s3 = 0.f;
#pragma unroll
        for (int f = 0; f < F_DIM; f += 4) {
            s0 = fmaf(sAcc[f + 0], Wout[(f + 0) * F_DIM + tid], s0);
            s1 = fmaf(sAcc[f + 1], Wout[(f + 1) * F_DIM + tid], s1);
            s2 = fmaf(sAcc[f + 2], Wout[(f + 2) * F_DIM + tid], s2);
            s3 = fmaf(sAcc[f + 3], Wout[(f + 3) * F_DIM + tid], s3);
        }
        out[blk * F_DIM + tid] = sspf((s0 + s1) + (s2 + s3) + bout[tid]);
    }
}

// ------------------------------- launcher ----------------------------------
extern "C" void kernel_launch(void* const* d_in, const int* in_sizes, int n_in,
                              void* d_out, int out_size)
{
    const float* x    = (const float*)d_in[0];
    const float* r_ij = (const float*)d_in[1];
    const float* mask = (const float*)d_in[2];
    const float* Wf1  = (const float*)d_in[3];
    const float* bf1  = (const float*)d_in[4];
    const float* Wf2  = (const float*)d_in[5];
    const float* bf2  = (const float*)d_in[6];
    const float* Win  = (const float*)d_in[7];
    const float* Wout = (const float*)d_in[8];
    const float* bout = (const float*)d_in[9];
    const int*   nj   = (const int*)d_in[10];
    const int*   nk   = (const int*)d_in[11];
    float* out = (float*)d_out;

    cudaFuncSetAttribute(cfconv_kernel,
                         cudaFuncAttributeMaxDynamicSharedMemorySize, SMEM_BYTES);

    in2f_kernel<<<B_DIM * A_DIM, F_DIM>>>(x, Win);
    cfconv_kernel<<<B_DIM * A_DIM, NT, SMEM_BYTES>>>(
        r_ij, mask, Wf1, bf1, Wf2, bf2, Wout, bout, nj, nk, out);
}

// round 7
// speedup vs baseline: 3.3651x; 1.1101x over previous
#include <cuda_runtime.h>
#include <cuda_fp16.h>
#include <cstdint>

// ---------------------------------------------------------------------------
// CFConvAngular: all-MMA + SMEM z-precompute. 256 threads, 2 CTAs/SM.
// GEMM1: H1^T[k][t] = Wf1^T @ R^T   (mma.sync, A in regs, B via ldmatrix, K=32)
// z-build: z[t][f] = y[j(t)][f]*y[k(t)][f]*m[t]  (coalesced float4, SMEM fp32)
// GEMM2: D^T[f][t] = Wf2^T @ H1^T   (mma.sync, A in regs, B via ldmatrix.trans)
// epilogue: acc[f] += (D+bf2[f]) * z[t][f]       (conflict-free LDS)
// out = ssp(acc @ Wout + bout)
// ---------------------------------------------------------------------------

#define B_DIM 2
#define A_DIM 512
#define T_DIM 512
#define F_DIM 128
#define R_DIM 25
#define TT    128
#define NTILES (T_DIM / TT)     // 4
#define NT    256               // 8 warps

__device__ float g_y[B_DIM * A_DIM * F_DIM];

__device__ __forceinline__ uint32_t smem_u32(const void* p) {
    uint32_t a;
    asm("{ .reg .u64 t; cvta.to.shared.u64 t, %1; cvt.u32.u64 %0, t; }" : "=r"(a) : "l"(p));
    return a;
}

// shifted softplus
__device__ __forceinline__ float sspf(float v) {
    float e = __expf(-fabsf(v));
    return fmaxf(v, 0.0f) + __logf(1.0f + e) - 0.69314718055994530942f;
}

// mma.sync m16n8k16 row.col f32 = f16*f16 + f32
__device__ __forceinline__ void mma16816(float& c0, float& c1, float& c2, float& c3,
                                         uint32_t a0, uint32_t a1, uint32_t a2, uint32_t a3,
                                         uint32_t b0, uint32_t b1) {
    asm volatile("mma.sync.aligned.m16n8k16.row.col.f32.f16.f16.f32 "
                 "{%0,%1,%2,%3}, {%4,%5,%6,%7}, {%8,%9}, {%0,%1,%2,%3};"
                 : "+f"(c0), "+f"(c1), "+f"(c2), "+f"(c3)
                 : "r"(a0), "r"(a1), "r"(a2), "r"(a3), "r"(b0), "r"(b1));
}

__device__ __forceinline__ void ldsm_x4(uint32_t& r0, uint32_t& r1,
                                        uint32_t& r2, uint32_t& r3, uint32_t addr) {
    asm volatile("ldmatrix.sync.aligned.m8n8.x4.shared.b16 {%0,%1,%2,%3}, [%4];"
                 : "=r"(r0), "=r"(r1), "=r"(r2), "=r"(r3) : "r"(addr));
}
__device__ __forceinline__ void ldsm_x4_t(uint32_t& r0, uint32_t& r1,
                                          uint32_t& r2, uint32_t& r3, uint32_t addr) {
    asm volatile("ldmatrix.sync.aligned.m8n8.x4.trans.shared.b16 {%0,%1,%2,%3}, [%4];"
                 : "=r"(r0), "=r"(r1), "=r"(r2), "=r"(r3) : "r"(addr));
}

__device__ __forceinline__ uint32_t h2u(float a, float b) {
    __half2 h = __floats2half2_rn(a, b);
    return *(uint32_t*)&h;
}

// ------------------------- kernel 1: y = x @ Win ---------------------------
__global__ void __launch_bounds__(F_DIM) in2f_kernel(
    const float* __restrict__ x, const float* __restrict__ Win)
{
    __shared__ float sx[F_DIM];
    const int tid = threadIdx.x;
    const int blk = blockIdx.x;
    sx[tid] = x[blk * F_DIM + tid];
    __syncthreads();
    float s0 = 0.f, s1 = 0.f, s2 = 0.f, s3 = 0.f;
#pragma unroll
    for (int i = 0; i < F_DIM; i += 4) {
        s0 = fmaf(sx[i + 0], Win[(i + 0) * F_DIM + tid], s0);
        s1 = fmaf(sx[i + 1], Win[(i + 1) * F_DIM + tid], s1);
        s2 = fmaf(sx[i + 2], Win[(i + 2) * F_DIM + tid], s2);
        s3 = fmaf(sx[i + 3], Win[(i + 3) * F_DIM + tid], s3);
    }
    g_y[blk * F_DIM + tid] = (s0 + s1) + (s2 + s3);
}

// ------------------------- main fused kernel -------------------------------
#define H1T_STRIDE_B 272                 // 128 k-rows x (128 t + pad) fp16
#define RH_STRIDE_B  80                  // 128 t-rows x (32 r + pad) fp16
#define Z_STRIDE     132                 // fp32 words per z row (bank-perm pad)
#define OFF_H1T  0                       // 34816
#define OFF_Z    34816                   // z fp32 128*132*4 = 67584 (r-tile
                                         //   staged in first 10240B, dead
                                         //   before z is written)
#define OFF_RH   OFF_Z
#define OFF_J    102400                  // 128 int
#define OFF_K    102912                  // 128 int
#define OFF_M    103424                  // 128 f32
#define OFF_ACC  103936                  // 128 f32
#define SMEM_BYTES 104448

__global__ void __launch_bounds__(NT, 2) cfconv_kernel(
    const float* __restrict__ r_ij, const float* __restrict__ mask,
    const float* __restrict__ Wf1, const float* __restrict__ bf1,
    const float* __restrict__ Wf2, const float* __restrict__ bf2,
    const float* __restrict__ Wout, const float* __restrict__ bout,
    const int* __restrict__ nj, const int* __restrict__ nk,
    float* __restrict__ out)
{
    extern __shared__ char smem[];
    const int tid  = threadIdx.x;
    const int lane = tid & 31;
    const int wid  = tid >> 5;            // 0..7
    const int g    = lane >> 2;           // 0..7
    const int tig  = lane & 3;            // 0..3
    const int blk  = blockIdx.x;
    const int b    = blk >> 9;

    int*   sJ   = (int*)(smem + OFF_J);
    int*   sK   = (int*)(smem + OFF_K);
    float* sM   = (float*)(smem + OFF_M);
    float* sAcc = (float*)(smem + OFF_ACC);
    float* sZ   = (float*)(smem + OFF_Z);
    const uint32_t sH1Tu = smem_u32(smem + OFF_H1T);
    const uint32_t sRHu  = smem_u32(smem + OFF_RH);
    __half* sRh = (__half*)(smem + OFF_RH);

    // ---- warp row-block (kc-rows in GEMM1, f-rows in GEMM2) ----
    const int rw   = wid * 16;
    const int m_lo = rw + g;
    const int m_hi = rw + g + 8;

    // ---- GEMM1 A-frags: Wf1^T[kc][r], K=32 (r>=25 zero), loop-invariant ----
    uint32_t aW[2][4];
#pragma unroll
    for (int s = 0; s < 2; s++) {
        const int r0 = s * 16 + 2 * tig;
#pragma unroll
        for (int q = 0; q < 4; q++) {
            const int rr = r0 + (q >> 1) * 8;
            const int cc = (q & 1) ? m_hi : m_lo;
            const float v0 = (rr     < R_DIM) ? Wf1[rr * F_DIM + cc]       : 0.f;
            const float v1 = (rr + 1 < R_DIM) ? Wf1[(rr + 1) * F_DIM + cc] : 0.f;
            aW[s][q] = h2u(v0, v1);
        }
    }

    // ---- GEMM2 A-frags: Wf2^T[f][k], loop-invariant ----
    uint32_t aA[8][4];
#pragma unroll
    for (int ks = 0; ks < 8; ks++) {
        const int k0 = ks * 16 + tig * 2;
        aA[ks][0] = h2u(Wf2[k0 * F_DIM + m_lo],       Wf2[(k0 + 1) * F_DIM + m_lo]);
        aA[ks][1] = h2u(Wf2[k0 * F_DIM + m_hi],       Wf2[(k0 + 1) * F_DIM + m_hi]);
        aA[ks][2] = h2u(Wf2[(k0 + 8) * F_DIM + m_lo], Wf2[(k0 + 9) * F_DIM + m_lo]);
        aA[ks][3] = h2u(Wf2[(k0 + 8) * F_DIM + m_hi], Wf2[(k0 + 9) * F_DIM + m_hi]);
    }
    const float bf1_lo = bf1[m_lo], bf1_hi = bf1[m_hi];
    const float bf2_lo = bf2[m_lo], bf2_hi = bf2[m_hi];

    // ldmatrix lane addresses
    const uint32_t rh_off  = (uint32_t)((lane & 7) * RH_STRIDE_B + (lane >> 3) * 16);
    const uint32_t h1t_off = (uint32_t)(((lane >> 3) * 8 + (lane & 7)) * H1T_STRIDE_B);

    const long   rbase = (long)blk * T_DIM * R_DIM;
    const int    tbase = blk * T_DIM;
    const float* ybase = g_y + (long)b * A_DIM * F_DIM;

    // z-build lane mapping: warp-uniform t, lane*4 = f4 (coalesced row loads)
    const int zb_tsub = tid >> 5;         // warp id = t offset within group of 8
    const int zb_f4   = lane * 4;

    float acc_lo = 0.f, acc_hi = 0.f;

    for (int tile = 0; tile < NTILES; ++tile) {
        // ---- stage r tile as fp16 [t][32] (r>=25 zeroed) + indices ----
        {
            const float* rsrc = r_ij + rbase + (long)tile * TT * R_DIM;
            for (int e = tid; e < TT * 32; e += NT) {
                const int t = e >> 5, r = e & 31;
                const float v = (r < R_DIM) ? rsrc[t * R_DIM + r] : 0.f;
                sRh[t * (RH_STRIDE_B / 2) + r] = __float2half_rn(v);
            }
            const int toff = tbase + tile * TT;
            if (tid < TT) {
                sJ[tid] = nj[toff + tid];
                sK[tid] = nk[toff + tid];
                sM[tid] = mask[toff + tid];
            }
        }
        __syncthreads();

        // ---- GEMM1: H1^T[kc][t] = Wf1^T @ R^T, +bf1, ssp, fp16 store ----
#pragma unroll 4
        for (int nb = 0; nb < 16; nb++) {
            uint32_t q0, q1, q2, q3;
            ldsm_x4(q0, q1, q2, q3, sRHu + (uint32_t)(nb * 8 * RH_STRIDE_B) + rh_off);
            float c0 = 0.f, c1 = 0.f, c2 = 0.f, c3 = 0.f;
            mma16816(c0, c1, c2, c3, aW[0][0], aW[0][1], aW[0][2], aW[0][3], q0, q1);
            mma16816(c0, c1, c2, c3, aW[1][0], aW[1][1], aW[1][2], aW[1][3], q2, q3);
            const int t0 = nb * 8 + 2 * tig;
            const uint32_t u_lo = h2u(sspf(c0 + bf1_lo), sspf(c1 + bf1_lo));
            const uint32_t u_hi = h2u(sspf(c2 + bf1_hi), sspf(c3 + bf1_hi));
            *(uint32_t*)(smem + OFF_H1T + m_lo * H1T_STRIDE_B + t0 * 2) = u_lo;
            *(uint32_t*)(smem + OFF_H1T + m_hi * H1T_STRIDE_B + t0 * 2) = u_hi;
        }
        __syncthreads();   // sRh consumed, H1T ready

        // ---- z-build: z[t][f] = y_j[f]*y_k[f]*m[t], coalesced float4 ----
#pragma unroll
        for (int i = 0; i < 16; i++) {
            const int t  = i * 8 + zb_tsub;           // warp-uniform
            const int jj = sJ[t];
            const int kk = sK[t];
            const float m = sM[t];
            const float4 yj = *(const float4*)(ybase + jj * F_DIM + zb_f4);
            const float4 yk = *(const float4*)(ybase + kk * F_DIM + zb_f4);
            float4 z;
            z.x = yj.x * yk.x * m;
            z.y = yj.y * yk.y * m;
            z.z = yj.z * yk.z * m;
            z.w = yj.w * yk.w * m;
            *(float4*)(sZ + t * Z_STRIDE + zb_f4) = z;
        }
        __syncthreads();   // z ready

        // ---- GEMM2 + epilogue over 16 t-blocks ----
#pragma unroll 2
        for (int nb = 0; nb < 16; nb++) {
            float c0 = 0.f, c1 = 0.f, c2 = 0.f, c3 = 0.f;
#pragma unroll
            for (int kq = 0; kq < 4; kq++) {
                uint32_t q0, q1, q2, q3;
                ldsm_x4_t(q0, q1, q2, q3,
                          sH1Tu + (uint32_t)(kq * 32 * H1T_STRIDE_B) + h1t_off
                                + (uint32_t)(nb * 16));
                mma16816(c0, c1, c2, c3,
                         aA[2 * kq][0], aA[2 * kq][1], aA[2 * kq][2], aA[2 * kq][3],
                         q0, q1);
                mma16816(c0, c1, c2, c3,
                         aA[2 * kq + 1][0], aA[2 * kq + 1][1], aA[2 * kq + 1][2], aA[2 * kq + 1][3],
                         q2, q3);
            }
            const int t_a = nb * 8 + tig * 2;
            const int t_b = t_a + 1;
            const float za_lo = sZ[t_a * Z_STRIDE + m_lo];
            const float zb_lo = sZ[t_b * Z_STRIDE + m_lo];
            const float za_hi = sZ[t_a * Z_STRIDE + m_hi];
            const float zb_hi = sZ[t_b * Z_STRIDE + m_hi];
            acc_lo = fmaf(c0 + bf2_lo, za_lo, acc_lo);
            acc_lo = fmaf(c1 + bf2_lo, zb_lo, acc_lo);
            acc_hi = fmaf(c2 + bf2_hi, za_hi, acc_hi);
            acc_hi = fmaf(c3 + bf2_hi, zb_hi, acc_hi);
        }
        __syncthreads();   // z/H1T consumed before next tile's staging
    }

    // ---- quad reduction and publish ----
    acc_lo += __shfl_xor_sync(0xFFFFFFFF, acc_lo, 1);
    acc_lo += __shfl_xor_sync(0xFFFFFFFF, acc_lo, 2);
    acc_hi += __shfl_xor_sync(0xFFFFFFFF, acc_hi, 1);
    acc_hi += __shfl_xor_sync(0xFFFFFFFF, acc_hi, 2);
    if (tig == 0) {
        sAcc[m_lo] = acc_lo;
        sAcc[m_hi] = acc_hi;
    }
    __syncthreads();

    // ---- f2out ----
    if (tid < F_DIM) {
        float s0 = 0.f, s1 = 0.f, s2 = 0.f, s3 = 0.f;
#pragma unroll
        for (int f = 0; f < F_DIM; f += 4) {
            s0 = fmaf(sAcc[f + 0], Wout[(f + 0) * F_DIM + tid], s0);
            s1 = fmaf(sAcc[f + 1], Wout[(f + 1) * F_DIM + tid], s1);
            s2 = fmaf(sAcc[f + 2], Wout[(f + 2) * F_DIM + tid], s2);
            s3 = fmaf(sAcc[f + 3], Wout[(f + 3) * F_DIM + tid], s3);
        }
        out[blk * F_DIM + tid] = sspf((s0 + s1) + (s2 + s3) + bout[tid]);
    }
}

// ------------------------------- launcher ----------------------------------
extern "C" void kernel_launch(void* const* d_in, const int* in_sizes, int n_in,
                              void* d_out, int out_size)
{
    const float* x    = (const float*)d_in[0];
    const float* r_ij = (const float*)d_in[1];
    const float* mask = (const float*)d_in[2];
    const float* Wf1  = (const float*)d_in[3];
    const float* bf1  = (const float*)d_in[4];
    const float* Wf2  = (const float*)d_in[5];
    const float* bf2  = (const float*)d_in[6];
    const float* Win  = (const float*)d_in[7];
    const float* Wout = (const float*)d_in[8];
    const float* bout = (const float*)d_in[9];
    const int*   nj   = (const int*)d_in[10];
    const int*   nk   = (const int*)d_in[11];
    float* out = (float*)d_out;

    cudaFuncSetAttribute(cfconv_kernel,
                         cudaFuncAttributeMaxDynamicSharedMemorySize, SMEM_BYTES);

    in2f_kernel<<<B_DIM * A_DIM, F_DIM>>>(x, Win);
    cfconv_kernel<<<B_DIM * A_DIM, NT, SMEM_BYTES>>>(
        r_ij, mask, Wf1, bf1, Wf2, bf2, Wout, bout, nj, nk, out);
}